// round 3
// baseline (speedup 1.0000x reference)
#include <cuda_runtime.h>
#include <cuda_bf16.h>
#include <math.h>

// Problem constants
#define NTOK   32768      // 32 * 32 * 32 tokens
#define CDIM   256
#define SCODE  1024
#define HW     1024       // 32*32 spatial per batch
#define BETA   0.25f

// ---------------- device scratch (no allocations allowed) ----------------
__device__ float        g_w2[SCODE];
__device__ int          g_idx[NTOK];
__device__ unsigned int g_hist[SCODE];
__device__ float        g_losspart[512];

// ---------------- kernel 0: w2 precompute + scratch zero ----------------
// w2[s] replicates XLA-CPU reduce: sequential scalar, separate mul/add (no fma)
__global__ void k_init(const float* __restrict__ emb) {
    int t = blockIdx.x * 256 + threadIdx.x;   // 0..1023
    const float* row = emb + (size_t)t * CDIM;
    float s = 0.f;
    for (int k = 0; k < CDIM; k++) {
        s = __fadd_rn(s, __fmul_rn(row[k], row[k]));
    }
    g_w2[t] = s;
    g_hist[t] = 0u;
    if (t < 512) g_losspart[t] = 0.f;
}

// ---------------- kernel 1: fused GEMM + argmin ----------------
// grid: 512 blocks (64 tokens each), block: (16,8) = 128 threads
// shared: Xs[256][64] k-major (64KB) + Es[64 codes][65 k] (16.25KB) + x2s[64]
#define ES_STRIDE 65

__global__ void __launch_bounds__(128) k_argmin(const float* __restrict__ x,
                                                const float* __restrict__ emb) {
    extern __shared__ float smem[];
    float* Xs  = smem;                       // [c][tok] : c*64 + tok
    float* Es  = smem + 256 * 64;            // [ss][kk] : ss*65 + kk
    float* x2s = smem + 256 * 64 + 64 * ES_STRIDE;  // [64]

    const int tx = threadIdx.x;       // 0..15  -> 4 codes each
    const int ty = threadIdx.y;       // 0..7   -> 8 tokens each
    const int t  = ty * 16 + tx;      // 0..127

    const int n0  = blockIdx.x * 64;
    const int b   = n0 >> 10;
    const int hw0 = n0 & 1023;
    const float* xb = x + (size_t)b * (CDIM * HW) + hw0;

    // Load X tile: Xs[c][tok], coalesced float4 along tok
#pragma unroll
    for (int i = 0; i < 32; i++) {
        int idx = t + i * 128;                 // 0..4095
        int c = idx >> 4;
        int t4 = (idx & 15) << 2;
        float4 v = *(const float4*)(xb + (size_t)c * HW + t4);
        *(float4*)(Xs + c * 64 + t4) = v;
    }
    __syncthreads();

    // x2 per token: sequential scalar sum of squares, separate mul/add
    // (replicates XLA-CPU reduce order). Threads 0..63 handle one token each.
    if (t < 64) {
        float s = 0.f;
        for (int c = 0; c < CDIM; c++) {
            float v = Xs[c * 64 + t];
            s = __fadd_rn(s, __fmul_rn(v, v));
        }
        x2s[t] = s;
    }
    __syncthreads();

    float x2v[8];
#pragma unroll
    for (int i = 0; i < 8; i++) x2v[i] = x2s[ty * 8 + i];

    float bestV[8];
    int   bestI[8];
#pragma unroll
    for (int i = 0; i < 8; i++) { bestV[i] = 3.4e38f; bestI[i] = 0; }

    for (int s0 = 0; s0 < SCODE; s0 += 64) {
        float acc[8][4];
#pragma unroll
        for (int i = 0; i < 8; i++)
#pragma unroll
            for (int j = 0; j < 4; j++) acc[i][j] = 0.f;

        for (int k0 = 0; k0 < CDIM; k0 += 64) {
            __syncthreads();   // previous Es consumers done
            // load Es chunk: 64 codes x 64 k, coalesced float4 along k
#pragma unroll
            for (int i = 0; i < 8; i++) {
                int idx = t + i * 128;          // 0..1023
                int ss = idx >> 4;
                int k4 = (idx & 15) << 2;
                float4 v = *(const float4*)(emb + (size_t)(s0 + ss) * CDIM + k0 + k4);
                float* dst = Es + ss * ES_STRIDE + k4;
                dst[0] = v.x; dst[1] = v.y; dst[2] = v.z; dst[3] = v.w;
            }
            __syncthreads();

            // sequential ascending-k FMA per output (replicates gemm accumulation)
#pragma unroll 8
            for (int kk = 0; kk < 64; kk++) {
                const float* xr = Xs + (k0 + kk) * 64 + ty * 8;
                float4 a0 = *(const float4*)(xr);
                float4 a1 = *(const float4*)(xr + 4);
                float a[8] = {a0.x, a0.y, a0.z, a0.w, a1.x, a1.y, a1.z, a1.w};
                float bb[4];
#pragma unroll
                for (int j = 0; j < 4; j++)
                    bb[j] = Es[(tx * 4 + j) * ES_STRIDE + kk];
#pragma unroll
                for (int i = 0; i < 8; i++)
#pragma unroll
                    for (int j = 0; j < 4; j++)
                        acc[i][j] = fmaf(a[i], bb[j], acc[i][j]);
            }
        }

        // d2 = fl(fl(x2 - 2*dot) + w2), exactly as reference elementwise chain.
        // 2*dot is exact (power of two), so x2 - 2*dot is a single rounding.
        float w2v[4];
#pragma unroll
        for (int j = 0; j < 4; j++) w2v[j] = g_w2[s0 + tx * 4 + j];
#pragma unroll
        for (int i = 0; i < 8; i++)
#pragma unroll
            for (int j = 0; j < 4; j++) {
                float t1 = __fadd_rn(x2v[i], -__fmul_rn(2.0f, acc[i][j]));
                float d  = __fadd_rn(t1, w2v[j]);
                if (d < bestV[i]) { bestV[i] = d; bestI[i] = s0 + tx * 4 + j; }
            }
    }

    // cross-tx reduction (reuse Es region), first-min (lowest index) tie-break
    __syncthreads();
    float* redV = Es;                       // 64 tokens * 16 tx
    int*   redI = (int*)(Es + 1024);
#pragma unroll
    for (int i = 0; i < 8; i++) {
        redV[(ty * 8 + i) * 16 + tx] = bestV[i];
        redI[(ty * 8 + i) * 16 + tx] = bestI[i];
    }
    __syncthreads();
    if (t < 64) {
        float bv = redV[t * 16];
        int   bi = redI[t * 16];
#pragma unroll
        for (int j = 1; j < 16; j++) {
            float v  = redV[t * 16 + j];
            int   ii = redI[t * 16 + j];
            if (v < bv || (v == bv && ii < bi)) { bv = v; bi = ii; }
        }
        g_idx[n0 + t] = bi;
        atomicAdd(&g_hist[bi], 1u);
    }
}

// ---------------- kernel 2: gather + straight-through write + loss partials ----
// grid 512 x 256 threads; 64 tokens per block; coalesced writes along hw
__global__ void k_gather(const float* __restrict__ x, const float* __restrict__ emb,
                         float* __restrict__ out) {
    const int n0  = blockIdx.x * 64;
    const int b   = n0 >> 10;
    const int hw0 = n0 & 1023;
    const int tok = threadIdx.x & 63;
    const int cc  = threadIdx.x >> 6;      // 0..3

    const int mi = g_idx[n0 + tok];
    const float* e = emb + (size_t)mi * CDIM;
    const size_t base = (size_t)b * (CDIM * HW) + hw0 + tok;

    float s = 0.f;
    for (int c = cc; c < CDIM; c += 4) {
        float v = __ldg(e + c);
        size_t off = base + (size_t)c * HW;
        float xv = x[off];
        // straight-through: out = xf + (q - xf), both roundings as in reference
        float diff = __fadd_rn(v, -xv);
        out[off] = __fadd_rn(xv, diff);
        // commitment loss uses (q - xf)^2
        s = fmaf(diff, diff, s);
    }

    __shared__ float red[256];
    red[threadIdx.x] = s;
    __syncthreads();
    for (int st = 128; st > 0; st >>= 1) {
        if (threadIdx.x < st) red[threadIdx.x] += red[threadIdx.x + st];
        __syncthreads();
    }
    if (threadIdx.x == 0) g_losspart[blockIdx.x] = red[0];
}

// ---------------- kernel 3: finalize loss + perplexity ----------------
__global__ void k_final(float* __restrict__ out, int out_size) {
    __shared__ float red[1024];
    const int t = threadIdx.x;

    float p = (float)g_hist[t] / (float)NTOK;
    red[t] = p * logf(p + 1e-6f);
    __syncthreads();
    for (int st = 512; st > 0; st >>= 1) {
        if (t < st) red[t] += red[t + st];
        __syncthreads();
    }
    float plogp = red[0];
    __syncthreads();

    red[t] = (t < 512) ? g_losspart[t] : 0.f;
    __syncthreads();
    for (int st = 512; st > 0; st >>= 1) {
        if (t < st) red[t] += red[t + st];
        __syncthreads();
    }
    if (t == 0) {
        out[out_size - 2] = BETA * (red[0] / (float)(NTOK * CDIM));
        out[out_size - 1] = expf(-plogp);
    }
}

// ---------------- launch ----------------
extern "C" void kernel_launch(void* const* d_in, const int* in_sizes, int n_in,
                              void* d_out, int out_size) {
    const float* x   = (const float*)d_in[0];   // [32,256,32,32]
    const float* emb = (const float*)d_in[1];   // [1024,256]
    float* out = (float*)d_out;

    k_init<<<4, 256>>>(emb);

    size_t smem = (size_t)(256 * 64 + 64 * ES_STRIDE + 64) * sizeof(float); // ~82.7KB
    cudaFuncSetAttribute(k_argmin, cudaFuncAttributeMaxDynamicSharedMemorySize, (int)smem);
    k_argmin<<<NTOK / 64, dim3(16, 8), smem>>>(x, emb);

    k_gather<<<NTOK / 64, 256>>>(x, emb, out);

    k_final<<<1, 1024>>>(out, out_size);
}

// round 4
// speedup vs baseline: 1.0278x; 1.0278x over previous
#include <cuda_runtime.h>
#include <cuda_bf16.h>
#include <math.h>

// Problem constants
#define NTOK   32768      // 32 * 32 * 32 tokens
#define CDIM   256
#define SCODE  1024
#define HW     1024       // 32*32 spatial per batch
#define BETA   0.25f

typedef unsigned long long u64;

// ---------------- packed fp32x2 helpers (sm_100+; bit-exact per lane) --------
__device__ __forceinline__ u64 pack2(float lo, float hi) {
    u64 r; asm("mov.b64 %0, {%1, %2};" : "=l"(r) : "f"(lo), "f"(hi)); return r;
}
__device__ __forceinline__ void unpack2(u64 v, float& lo, float& hi) {
    asm("mov.b64 {%0, %1}, %2;" : "=f"(lo), "=f"(hi) : "l"(v));
}
__device__ __forceinline__ u64 fma2(u64 a, u64 b, u64 c) {
    u64 d; asm("fma.rn.f32x2 %0, %1, %2, %3;" : "=l"(d) : "l"(a), "l"(b), "l"(c)); return d;
}

// ---------------- device scratch (no allocations allowed) ----------------
__device__ float        g_w2[SCODE];
__device__ int          g_idx[NTOK];
__device__ unsigned int g_hist[SCODE];
__device__ float        g_losspart[512];

// ---------------- kernel 0: w2 precompute + scratch zero ----------------
// w2[s] replicates XLA-CPU reduce: sequential scalar, separate mul/add (no fma)
__global__ void k_init(const float* __restrict__ emb) {
    int t = blockIdx.x * 256 + threadIdx.x;   // 0..1023
    const float* row = emb + (size_t)t * CDIM;
    float s = 0.f;
    for (int k = 0; k < CDIM; k++) {
        s = __fadd_rn(s, __fmul_rn(row[k], row[k]));
    }
    g_w2[t] = s;
    g_hist[t] = 0u;
    if (t < 512) g_losspart[t] = 0.f;
}

// ---------------- kernel 1: fused GEMM + argmin (packed f32x2 FMA) -----------
// grid: 512 blocks (64 tokens each), block: (16,8) = 128 threads
// shared: Xs[256][64] k-major (64KB) + Es[64 codes][65 k] (16.25KB) + x2s[64]
#define ES_STRIDE 65

__global__ void __launch_bounds__(128) k_argmin(const float* __restrict__ x,
                                                const float* __restrict__ emb) {
    extern __shared__ float smem[];
    float* Xs  = smem;                       // [c][tok] : c*64 + tok
    float* Es  = smem + 256 * 64;            // [ss][kk] : ss*65 + kk
    float* x2s = smem + 256 * 64 + 64 * ES_STRIDE;  // [64]

    const int tx = threadIdx.x;       // 0..15  -> 4 codes each
    const int ty = threadIdx.y;       // 0..7   -> 8 tokens each
    const int t  = ty * 16 + tx;      // 0..127

    const int n0  = blockIdx.x * 64;
    const int b   = n0 >> 10;
    const int hw0 = n0 & 1023;
    const float* xb = x + (size_t)b * (CDIM * HW) + hw0;

    // Load X tile: Xs[c][tok], coalesced float4 along tok
#pragma unroll
    for (int i = 0; i < 32; i++) {
        int idx = t + i * 128;                 // 0..4095
        int c = idx >> 4;
        int t4 = (idx & 15) << 2;
        float4 v = *(const float4*)(xb + (size_t)c * HW + t4);
        *(float4*)(Xs + c * 64 + t4) = v;
    }
    __syncthreads();

    // x2 per token: sequential scalar sum of squares, separate mul/add
    // (replicates XLA-CPU reduce order). Threads 0..63 handle one token each.
    if (t < 64) {
        float s = 0.f;
        for (int c = 0; c < CDIM; c++) {
            float v = Xs[c * 64 + t];
            s = __fadd_rn(s, __fmul_rn(v, v));
        }
        x2s[t] = s;
    }
    __syncthreads();

    float x2v[8];
#pragma unroll
    for (int i = 0; i < 8; i++) x2v[i] = x2s[ty * 8 + i];

    float bestV[8];
    int   bestI[8];
#pragma unroll
    for (int i = 0; i < 8; i++) { bestV[i] = 3.4e38f; bestI[i] = 0; }

    for (int s0 = 0; s0 < SCODE; s0 += 64) {
        // acc2[i][j]: token-pair i (tokens 2i,2i+1 of this thread's 8), code j
        u64 acc2[4][4];
#pragma unroll
        for (int i = 0; i < 4; i++)
#pragma unroll
            for (int j = 0; j < 4; j++) acc2[i][j] = 0ull;

        for (int k0 = 0; k0 < CDIM; k0 += 64) {
            __syncthreads();   // previous Es consumers done
            // load Es chunk: 64 codes x 64 k, coalesced float4 along k
#pragma unroll
            for (int i = 0; i < 8; i++) {
                int idx = t + i * 128;          // 0..1023
                int ss = idx >> 4;
                int k4 = (idx & 15) << 2;
                float4 v = *(const float4*)(emb + (size_t)(s0 + ss) * CDIM + k0 + k4);
                float* dst = Es + ss * ES_STRIDE + k4;
                dst[0] = v.x; dst[1] = v.y; dst[2] = v.z; dst[3] = v.w;
            }
            __syncthreads();

            // sequential ascending-k packed FMA: each fma.rn.f32x2 does two
            // bit-exact fp32 FMAs (two adjacent tokens), same accumulation
            // chain per output as the reference gemm.
#pragma unroll 8
            for (int kk = 0; kk < 64; kk++) {
                const u64* xr2 = (const u64*)(Xs + (k0 + kk) * 64 + ty * 8);
                u64 a2[4];
                a2[0] = xr2[0]; a2[1] = xr2[1]; a2[2] = xr2[2]; a2[3] = xr2[3];
                u64 b2[4];
#pragma unroll
                for (int j = 0; j < 4; j++) {
                    float bv = Es[(tx * 4 + j) * ES_STRIDE + kk];
                    b2[j] = pack2(bv, bv);
                }
#pragma unroll
                for (int i = 0; i < 4; i++)
#pragma unroll
                    for (int j = 0; j < 4; j++)
                        acc2[i][j] = fma2(a2[i], b2[j], acc2[i][j]);
            }
        }

        // d2 = fl(fl(x2 - 2*dot) + w2), exactly as reference elementwise chain.
        float w2v[4];
#pragma unroll
        for (int j = 0; j < 4; j++) w2v[j] = g_w2[s0 + tx * 4 + j];
#pragma unroll
        for (int i = 0; i < 4; i++)
#pragma unroll
            for (int j = 0; j < 4; j++) {
                float dlo, dhi;
                unpack2(acc2[i][j], dlo, dhi);
                {
                    float t1 = __fadd_rn(x2v[2 * i], -__fmul_rn(2.0f, dlo));
                    float d  = __fadd_rn(t1, w2v[j]);
                    if (d < bestV[2 * i]) { bestV[2 * i] = d; bestI[2 * i] = s0 + tx * 4 + j; }
                }
                {
                    float t1 = __fadd_rn(x2v[2 * i + 1], -__fmul_rn(2.0f, dhi));
                    float d  = __fadd_rn(t1, w2v[j]);
                    if (d < bestV[2 * i + 1]) { bestV[2 * i + 1] = d; bestI[2 * i + 1] = s0 + tx * 4 + j; }
                }
            }
    }

    // cross-tx reduction (reuse Es region), first-min (lowest index) tie-break
    __syncthreads();
    float* redV = Es;                       // 64 tokens * 16 tx
    int*   redI = (int*)(Es + 1024);
#pragma unroll
    for (int i = 0; i < 8; i++) {
        redV[(ty * 8 + i) * 16 + tx] = bestV[i];
        redI[(ty * 8 + i) * 16 + tx] = bestI[i];
    }
    __syncthreads();
    if (t < 64) {
        float bv = redV[t * 16];
        int   bi = redI[t * 16];
#pragma unroll
        for (int j = 1; j < 16; j++) {
            float v  = redV[t * 16 + j];
            int   ii = redI[t * 16 + j];
            if (v < bv || (v == bv && ii < bi)) { bv = v; bi = ii; }
        }
        g_idx[n0 + t] = bi;
        atomicAdd(&g_hist[bi], 1u);
    }
}

// ---------------- kernel 2: gather + straight-through write + loss partials ----
// grid 512 x 256 threads; 64 tokens per block; coalesced writes along hw
__global__ void k_gather(const float* __restrict__ x, const float* __restrict__ emb,
                         float* __restrict__ out) {
    const int n0  = blockIdx.x * 64;
    const int b   = n0 >> 10;
    const int hw0 = n0 & 1023;
    const int tok = threadIdx.x & 63;
    const int cc  = threadIdx.x >> 6;      // 0..3

    const int mi = g_idx[n0 + tok];
    const float* e = emb + (size_t)mi * CDIM;
    const size_t base = (size_t)b * (CDIM * HW) + hw0 + tok;

    float s = 0.f;
    for (int c = cc; c < CDIM; c += 4) {
        float v = __ldg(e + c);
        size_t off = base + (size_t)c * HW;
        float xv = x[off];
        // straight-through: out = xf + (q - xf), both roundings as in reference
        float diff = __fadd_rn(v, -xv);
        out[off] = __fadd_rn(xv, diff);
        // commitment loss uses (q - xf)^2
        s = fmaf(diff, diff, s);
    }

    __shared__ float red[256];
    red[threadIdx.x] = s;
    __syncthreads();
    for (int st = 128; st > 0; st >>= 1) {
        if (threadIdx.x < st) red[threadIdx.x] += red[threadIdx.x + st];
        __syncthreads();
    }
    if (threadIdx.x == 0) g_losspart[blockIdx.x] = red[0];
}

// ---------------- kernel 3: finalize loss + perplexity ----------------
__global__ void k_final(float* __restrict__ out, int out_size) {
    __shared__ float red[1024];
    const int t = threadIdx.x;

    float p = (float)g_hist[t] / (float)NTOK;
    red[t] = p * logf(p + 1e-6f);
    __syncthreads();
    for (int st = 512; st > 0; st >>= 1) {
        if (t < st) red[t] += red[t + st];
        __syncthreads();
    }
    float plogp = red[0];
    __syncthreads();

    red[t] = (t < 512) ? g_losspart[t] : 0.f;
    __syncthreads();
    for (int st = 512; st > 0; st >>= 1) {
        if (t < st) red[t] += red[t + st];
        __syncthreads();
    }
    if (t == 0) {
        out[out_size - 2] = BETA * (red[0] / (float)(NTOK * CDIM));
        out[out_size - 1] = expf(-plogp);
    }
}

// ---------------- launch ----------------
extern "C" void kernel_launch(void* const* d_in, const int* in_sizes, int n_in,
                              void* d_out, int out_size) {
    const float* x   = (const float*)d_in[0];   // [32,256,32,32]
    const float* emb = (const float*)d_in[1];   // [1024,256]
    float* out = (float*)d_out;

    k_init<<<4, 256>>>(emb);

    size_t smem = (size_t)(256 * 64 + 64 * ES_STRIDE + 64) * sizeof(float); // ~82.7KB
    cudaFuncSetAttribute(k_argmin, cudaFuncAttributeMaxDynamicSharedMemorySize, (int)smem);
    k_argmin<<<NTOK / 64, dim3(16, 8), smem>>>(x, emb);

    k_gather<<<NTOK / 64, 256>>>(x, emb, out);

    k_final<<<1, 1024>>>(out, out_size);
}